// round 3
// baseline (speedup 1.0000x reference)
#include <cuda_runtime.h>
#include <cuda_bf16.h>
#include <cstdint>

// ---------------------------------------------------------------------------
// Problem constants: B=128, D=2048, M=8192, C=2048, K_ITERS=1024, TAU=0.5
// JAX PRNG: threefry2x32 with jax_threefry_partitionable=True semantics:
//   random_bits(key,32,shape): elem i -> cipher(key, x0=0, x1=i), bits=o0^o1
//   split(key): key_j = (o0,o1) of cipher(key, x0=0, x1=j); new=j0, sub=j1
// ---------------------------------------------------------------------------
#define B_DIM 128
#define D_DIM 2048
#define M_DIM 8192
#define C_DIM 2048
#define K_ITERS 1024
#define F32_TINY 1.17549435e-38f

// Scratch (static device globals; no runtime allocation)
__device__ float d_buf[B_DIM * M_DIM];      // raw GEMM output
__device__ float d_h[B_DIM * M_DIM];        // BN+ReLU output
__device__ float d_logits[B_DIM * C_DIM];   // final BN output
__device__ uint32_t d_subkeys[2 * K_ITERS]; // per-iteration threefry subkeys

// ---------------------------------------------------------------------------
// threefry2x32 (matches JAX exactly)
// ---------------------------------------------------------------------------
__device__ __forceinline__ void tf_round(uint32_t& x0, uint32_t& x1, int d) {
    x0 += x1;
    x1 = __funnelshift_l(x1, x1, d);
    x1 ^= x0;
}

__device__ __forceinline__ void threefry2x32(uint32_t k0, uint32_t k1, uint32_t k2,
                                             uint32_t x0, uint32_t x1,
                                             uint32_t& o0, uint32_t& o1) {
    x0 += k0; x1 += k1;
    tf_round(x0, x1, 13); tf_round(x0, x1, 15); tf_round(x0, x1, 26); tf_round(x0, x1, 6);
    x0 += k1; x1 += k2 + 1u;
    tf_round(x0, x1, 17); tf_round(x0, x1, 29); tf_round(x0, x1, 16); tf_round(x0, x1, 24);
    x0 += k2; x1 += k0 + 2u;
    tf_round(x0, x1, 13); tf_round(x0, x1, 15); tf_round(x0, x1, 26); tf_round(x0, x1, 6);
    x0 += k0; x1 += k1 + 3u;
    tf_round(x0, x1, 17); tf_round(x0, x1, 29); tf_round(x0, x1, 16); tf_round(x0, x1, 24);
    x0 += k1; x1 += k2 + 4u;
    tf_round(x0, x1, 13); tf_round(x0, x1, 15); tf_round(x0, x1, 26); tf_round(x0, x1, 6);
    x0 += k2; x1 += k0 + 5u;
    o0 = x0; o1 = x1;
}

// Partitionable-foldlike key chain: key = key(42) = (0,42).
// Each iteration: lane l in {0,1} ciphers x=(0, l) under current key.
//   new key = (o0,o1) of lane 0;  sub = (o0,o1) of lane 1.
// Run on one warp, fused into the layer-2 GEMM launch.
__device__ void keychain_warp() {
    if (threadIdx.x >= 32) return;
    const unsigned FULL = 0xffffffffu;
    uint32_t lane = threadIdx.x & 31;
    uint32_t k0 = 0u, k1 = 42u;
    for (int t = 0; t < K_ITERS; t++) {
        uint32_t kx = k0 ^ k1 ^ 0x1BD11BDAu;
        uint32_t o0, o1;
        threefry2x32(k0, k1, kx, 0u, lane, o0, o1);
        if (lane == 1) {
            d_subkeys[2 * t]     = o0;
            d_subkeys[2 * t + 1] = o1;
        }
        k0 = __shfl_sync(FULL, o0, 0);
        k1 = __shfl_sync(FULL, o1, 0);
    }
}

// ---------------------------------------------------------------------------
// GEMM: Y[128, N] = A[128, K] @ W[N, K]^T + bias, fp32
// 256 threads (16x16), thread tile 8 x TN, block tile 128 x (16*TN), KT=16
// ---------------------------------------------------------------------------
template <int TN>
__global__ void __launch_bounds__(256) gemm_bias_kernel(
    const float* __restrict__ A, const float* __restrict__ W,
    const float* __restrict__ bias, float* __restrict__ Y,
    int K, int N, int with_keys) {
    constexpr int BN = 16 * TN;
    constexpr int KT = 16;

    if (with_keys && blockIdx.x == (unsigned)(gridDim.x - 1)) {
        keychain_warp();
        return;
    }

    __shared__ float As[KT][129];
    __shared__ float Ws[KT][BN + 1];

    const int tid = threadIdx.x;
    const int tx = tid & 15;
    const int ty = tid >> 4;
    const int colBase = blockIdx.x * BN;

    float acc[8][TN];
#pragma unroll
    for (int m = 0; m < 8; m++)
#pragma unroll
        for (int n = 0; n < TN; n++) acc[m][n] = 0.0f;

    for (int k0 = 0; k0 < K; k0 += KT) {
#pragma unroll
        for (int p = 0; p < 8; p++) {
            int idx = tid + p * 256;           // 2048 elements of A tile
            int k = idx & 15, r = idx >> 4;
            As[k][r] = A[r * K + k0 + k];
        }
#pragma unroll
        for (int p = 0; p < BN / 16; p++) {
            int idx = tid + p * 256;           // BN*16 elements of W tile
            int k = idx & 15, n = idx >> 4;
            Ws[k][n] = W[(size_t)(colBase + n) * K + k0 + k];
        }
        __syncthreads();
#pragma unroll
        for (int k = 0; k < KT; k++) {
            float a[8], w[TN];
#pragma unroll
            for (int m = 0; m < 8; m++) a[m] = As[k][ty + m * 16];
#pragma unroll
            for (int n = 0; n < TN; n++) w[n] = Ws[k][tx + n * 16];
#pragma unroll
            for (int m = 0; m < 8; m++)
#pragma unroll
                for (int n = 0; n < TN; n++) acc[m][n] += a[m] * w[n];
        }
        __syncthreads();
    }

#pragma unroll
    for (int m = 0; m < 8; m++) {
        int row = ty + m * 16;
#pragma unroll
        for (int n = 0; n < TN; n++) {
            int col = colBase + tx + n * 16;
            Y[row * N + col] = acc[m][n] + bias[col];
        }
    }
}

// ---------------------------------------------------------------------------
// Training-mode BatchNorm1d over batch dim (128 rows), optional affine+ReLU
// ---------------------------------------------------------------------------
__global__ void bn_kernel(const float* __restrict__ X, const float* __restrict__ gamma,
                          const float* __restrict__ beta, float* __restrict__ Y,
                          int N, int affine_relu) {
    int c = blockIdx.x * blockDim.x + threadIdx.x;
    if (c >= N) return;
    float s = 0.0f;
#pragma unroll 8
    for (int r = 0; r < B_DIM; r++) s += X[r * N + c];
    float mu = s * (1.0f / B_DIM);
    float v = 0.0f;
#pragma unroll 8
    for (int r = 0; r < B_DIM; r++) {
        float dd = X[r * N + c] - mu;
        v += dd * dd;
    }
    float rstd = rsqrtf(v * (1.0f / B_DIM) + 1e-5f);
    float ga = 1.0f, be = 0.0f;
    if (affine_relu) { ga = gamma[c]; be = beta[c]; }
#pragma unroll 8
    for (int r = 0; r < B_DIM; r++) {
        float y = (X[r * N + c] - mu) * rstd;
        y = y * ga + be;
        if (affine_relu) y = fmaxf(y, 0.0f);
        Y[r * N + c] = y;
    }
}

// ---------------------------------------------------------------------------
// Gumbel value from raw threefry bits (JAX uniform->gumbel, accurate near u=1)
// u = bits>>9 | 0x3f800000 bitcast - 1, clamped to tiny; g = -log(-log(u))
// ---------------------------------------------------------------------------
__device__ __forceinline__ float gumbel_from_bits(uint32_t bits) {
    uint32_t mb = bits >> 9;
    float f = __uint_as_float(mb | 0x3f800000u) - 1.0f;   // exact m * 2^-23
    float u = fmaxf(F32_TINY, f + F32_TINY);
    float d = 1.0f - f;                                    // exact
    // log(1-d) series for d < 2^-8 (inner-log relative accuracy where it matters)
    float Ls = -(d * (1.0f + d * (0.5f + d * (0.33333334f + d * 0.25f))));
    float L = (d < 0.00390625f) ? Ls : __logf(u);
    return -__logf(-L);
}

// ---------------------------------------------------------------------------
// K=1024 sequential gumbel-softmax scan.
// One block per output row r; 512 threads x 4 columns.
// Partitionable threefry: element i = r*2048+c -> cipher(sub, 0, i), o0^o1.
// ---------------------------------------------------------------------------
__global__ void __launch_bounds__(512, 1) gumbel_scan_kernel(
    const float* __restrict__ logits, float* __restrict__ z_out) {
    const int r = blockIdx.x;
    const int tid = threadIdx.x;
    const int lane = tid & 31;
    const int wid = tid >> 5;
    const uint32_t ibase = (uint32_t)r * 2048u + (uint32_t)tid;

    __shared__ float redA[16];
    __shared__ float redB[16];

    float mask[4], z[4];
#pragma unroll
    for (int i = 0; i < 4; i++) {
        int c = tid + 512 * i;
        mask[i] = logits[r * C_DIM + c];
        z[i] = 0.0f;
    }

    for (int t = 0; t < K_ITERS; t++) {
        const uint32_t k0 = d_subkeys[2 * t];
        const uint32_t k1 = d_subkeys[2 * t + 1];
        const uint32_t k2 = k0 ^ k1 ^ 0x1BD11BDAu;

        float s[4];
#pragma unroll
        for (int i = 0; i < 4; i++) {
            uint32_t idx = ibase + 512u * (uint32_t)i;
            uint32_t o0, o1;
            threefry2x32(k0, k1, k2, 0u, idx, o0, o1);
            float g = gumbel_from_bits(o0 ^ o1);
            s[i] = (mask[i] + g) * 2.0f;   // /TAU, TAU=0.5 (exact)
        }

        // block max over 2048
        float mx = fmaxf(fmaxf(s[0], s[1]), fmaxf(s[2], s[3]));
#pragma unroll
        for (int o = 16; o > 0; o >>= 1) mx = fmaxf(mx, __shfl_xor_sync(0xffffffffu, mx, o));
        if (lane == 0) redA[wid] = mx;
        __syncthreads();
        mx = redA[0];
#pragma unroll
        for (int w = 1; w < 16; w++) mx = fmaxf(mx, redA[w]);

        float e[4];
        float sm = 0.0f;
#pragma unroll
        for (int i = 0; i < 4; i++) {
            e[i] = __expf(s[i] - mx);
            sm += e[i];
        }
#pragma unroll
        for (int o = 16; o > 0; o >>= 1) sm += __shfl_xor_sync(0xffffffffu, sm, o);
        if (lane == 0) redB[wid] = sm;
        __syncthreads();
        sm = redB[0];
#pragma unroll
        for (int w = 1; w < 16; w++) sm += redB[w];

        float inv = __fdividef(1.0f, sm);
#pragma unroll
        for (int i = 0; i < 4; i++) {
            mask[i] = e[i] * inv;
            z[i] = fmaxf(z[i], mask[i]);
        }
        // redB reads are protected by the next iteration's first barrier
        // before redA is rewritten.
    }

#pragma unroll
    for (int i = 0; i < 4; i++) z_out[r * C_DIM + tid + 512 * i] = z[i];
}

// ---------------------------------------------------------------------------
// Launch
// ---------------------------------------------------------------------------
extern "C" void kernel_launch(void* const* d_in, const int* in_sizes, int n_in,
                              void* d_out, int out_size) {
    const float* f   = (const float*)d_in[0];
    const float* w1  = (const float*)d_in[1];
    const float* b1  = (const float*)d_in[2];
    const float* g1  = (const float*)d_in[3];
    const float* be1 = (const float*)d_in[4];
    const float* w2  = (const float*)d_in[5];
    const float* b2  = (const float*)d_in[6];
    const float* g2  = (const float*)d_in[7];
    const float* be2 = (const float*)d_in[8];
    const float* w3  = (const float*)d_in[9];
    const float* b3  = (const float*)d_in[10];
    float* out = (float*)d_out;

    float* buf;    cudaGetSymbolAddress((void**)&buf, d_buf);
    float* h;      cudaGetSymbolAddress((void**)&h, d_h);
    float* logits; cudaGetSymbolAddress((void**)&logits, d_logits);

    // Layer 1: [128,2048] @ [8192,2048]^T -> [128,8192]
    gemm_bias_kernel<4><<<M_DIM / 64, 256>>>(f, w1, b1, buf, D_DIM, M_DIM, 0);
    bn_kernel<<<M_DIM / 256, 256>>>(buf, g1, be1, h, M_DIM, 1);

    // Layer 2: [128,8192] @ [8192,8192]^T -> [128,8192]; +1 block runs keychain
    gemm_bias_kernel<4><<<M_DIM / 64 + 1, 256>>>(h, w2, b2, buf, M_DIM, M_DIM, 1);
    bn_kernel<<<M_DIM / 256, 256>>>(buf, g2, be2, h, M_DIM, 1);

    // Layer 3: [128,8192] @ [2048,8192]^T -> [128,2048]; BN affine=False
    gemm_bias_kernel<1><<<C_DIM / 16, 256>>>(h, w3, b3, buf, M_DIM, C_DIM, 0);
    bn_kernel<<<C_DIM / 256, 256>>>(buf, nullptr, nullptr, logits, C_DIM, 0);

    // K=1024 gumbel-softmax scan
    gumbel_scan_kernel<<<B_DIM, 512>>>(logits, out);
}

// round 5
// speedup vs baseline: 1.7252x; 1.7252x over previous
#include <cuda_runtime.h>
#include <cuda_bf16.h>
#include <cstdint>

// ---------------------------------------------------------------------------
// B=128, D=2048, M=8192, C=2048, K_ITERS=1024, TAU=0.5
// ---------------------------------------------------------------------------
#define B_DIM 128
#define D_DIM 2048
#define M_DIM 8192
#define C_DIM 2048
#define K_ITERS 1024
#define F32_TINY 1.17549435e-38f

__device__ float d_h1[B_DIM * M_DIM];
__device__ float d_h2[B_DIM * M_DIM];
__device__ float d_logits[B_DIM * C_DIM];
__device__ uint32_t d_subkeys[2 * K_ITERS];
__device__ uint32_t d_key_ready;   // reset each replay by reset_kernel

// ---------------------------------------------------------------------------
// PTX helpers (all portable to compute_103: mma.sync/ldmatrix are sm_80+)
// ---------------------------------------------------------------------------
__device__ __forceinline__ uint32_t ld_acquire_u32(const uint32_t* p) {
    uint32_t v;
    asm volatile("ld.acquire.gpu.global.u32 %0, [%1];" : "=r"(v) : "l"(p) : "memory");
    return v;
}
__device__ __forceinline__ void st_release_u32(uint32_t* p, uint32_t v) {
    asm volatile("st.release.gpu.global.u32 [%0], %1;" :: "l"(p), "r"(v) : "memory");
}
__device__ __forceinline__ void ldsm_x4(uint32_t& r0, uint32_t& r1, uint32_t& r2,
                                        uint32_t& r3, uint32_t addr) {
    asm volatile("ldmatrix.sync.aligned.m8n8.x4.shared.b16 {%0,%1,%2,%3}, [%4];"
                 : "=r"(r0), "=r"(r1), "=r"(r2), "=r"(r3) : "r"(addr));
}
__device__ __forceinline__ void ldsm_x2(uint32_t& r0, uint32_t& r1, uint32_t addr) {
    asm volatile("ldmatrix.sync.aligned.m8n8.x2.shared.b16 {%0,%1}, [%2];"
                 : "=r"(r0), "=r"(r1) : "r"(addr));
}
__device__ __forceinline__ void mma_bf16(float* c, const uint32_t* a, const uint32_t* b) {
    asm volatile(
        "mma.sync.aligned.m16n8k16.row.col.f32.bf16.bf16.f32 "
        "{%0,%1,%2,%3}, {%4,%5,%6,%7}, {%8,%9}, {%0,%1,%2,%3};"
        : "+f"(c[0]), "+f"(c[1]), "+f"(c[2]), "+f"(c[3])
        : "r"(a[0]), "r"(a[1]), "r"(a[2]), "r"(a[3]), "r"(b[0]), "r"(b[1]));
}

// ---------------------------------------------------------------------------
// threefry2x32 (JAX-exact, partitionable semantics)
// ---------------------------------------------------------------------------
__device__ __forceinline__ void tf_round(uint32_t& x0, uint32_t& x1, int d) {
    x0 += x1;
    x1 = __funnelshift_l(x1, x1, d);
    x1 ^= x0;
}
__device__ __forceinline__ void threefry2x32(uint32_t k0, uint32_t k1, uint32_t k2,
                                             uint32_t x0, uint32_t x1,
                                             uint32_t& o0, uint32_t& o1) {
    x0 += k0; x1 += k1;
    tf_round(x0, x1, 13); tf_round(x0, x1, 15); tf_round(x0, x1, 26); tf_round(x0, x1, 6);
    x0 += k1; x1 += k2 + 1u;
    tf_round(x0, x1, 17); tf_round(x0, x1, 29); tf_round(x0, x1, 16); tf_round(x0, x1, 24);
    x0 += k2; x1 += k0 + 2u;
    tf_round(x0, x1, 13); tf_round(x0, x1, 15); tf_round(x0, x1, 26); tf_round(x0, x1, 6);
    x0 += k0; x1 += k1 + 3u;
    tf_round(x0, x1, 17); tf_round(x0, x1, 29); tf_round(x0, x1, 16); tf_round(x0, x1, 24);
    x0 += k1; x1 += k2 + 4u;
    tf_round(x0, x1, 13); tf_round(x0, x1, 15); tf_round(x0, x1, 26); tf_round(x0, x1, 6);
    x0 += k2; x1 += k0 + 5u;
    o0 = x0; o1 = x1;
}

// ---------------------------------------------------------------------------
// GEMM(+fused BN/ReLU): Y[128, NOUT], block tile 128 x 64, BK=64.
// A[128,K], W[N,K] both k-major fp32, split to bf16 hi/lo; 3-pass mma.sync.
// smem pitch 144B per 64-col row (conflict-free for ldmatrix: r*144 % 128
// covers all eight 16B banks).
// ---------------------------------------------------------------------------
#define PITCH 144
#define OFF_AH 0
#define OFF_AL 18432
#define OFF_WH 36864
#define OFF_WL 46080
#define GEMM_SMEM_BYTES 55296

__device__ __forceinline__ void store_split(char* hbase, char* lbase, int row, int c4,
                                            float4 v) {
    __nv_bfloat16 h0 = __float2bfloat16(v.x);
    __nv_bfloat16 h1 = __float2bfloat16(v.y);
    __nv_bfloat16 h2 = __float2bfloat16(v.z);
    __nv_bfloat16 h3 = __float2bfloat16(v.w);
    __nv_bfloat16 l0 = __float2bfloat16(v.x - __bfloat162float(h0));
    __nv_bfloat16 l1 = __float2bfloat16(v.y - __bfloat162float(h1));
    __nv_bfloat16 l2 = __float2bfloat16(v.z - __bfloat162float(h2));
    __nv_bfloat16 l3 = __float2bfloat16(v.w - __bfloat162float(h3));
    uint32_t hi0 = ((uint32_t)__bfloat16_as_ushort(h1) << 16) | __bfloat16_as_ushort(h0);
    uint32_t hi1 = ((uint32_t)__bfloat16_as_ushort(h3) << 16) | __bfloat16_as_ushort(h2);
    uint32_t lo0 = ((uint32_t)__bfloat16_as_ushort(l1) << 16) | __bfloat16_as_ushort(l0);
    uint32_t lo1 = ((uint32_t)__bfloat16_as_ushort(l3) << 16) | __bfloat16_as_ushort(l2);
    uint32_t off = (uint32_t)(row * PITCH + c4 * 8);
    *(uint2*)(hbase + off) = make_uint2(hi0, hi1);
    *(uint2*)(lbase + off) = make_uint2(lo0, lo1);
}

template <bool AFFINE_RELU>
__global__ void __launch_bounds__(256, 1) gemm_bn_kernel(
    const float* __restrict__ A, const float* __restrict__ W,
    const float* __restrict__ gamma, const float* __restrict__ beta,
    float* __restrict__ Y, int K, int NOUT) {
    extern __shared__ char sm[];
    char* Ah = sm + OFF_AH;
    char* Al = sm + OFF_AL;
    char* Wh = sm + OFF_WH;
    char* Wl = sm + OFF_WL;

    const int tid = threadIdx.x;
    const int wid = tid >> 5;
    const int lane = tid & 31;
    const int colBase = blockIdx.x * 64;

    // warp tile: 64 rows x 16 cols
    const int row0 = (wid >> 2) * 64;
    const int col0 = (wid & 3) * 16;
    // ldmatrix lane addressing
    const int a_sub = lane >> 3;
    const int a_row = (a_sub & 1) * 8 + (lane & 7);
    const int a_kh = (a_sub >> 1) * 16;             // byte offset for k-half
    const int b_nrow = lane & 7;
    const int b_kh = ((lane >> 3) & 1) * 16;

    float acc[4][2][4];
#pragma unroll
    for (int mt = 0; mt < 4; mt++)
#pragma unroll
        for (int nt = 0; nt < 2; nt++)
#pragma unroll
            for (int i = 0; i < 4; i++) acc[mt][nt][i] = 0.0f;

    const int nch = K >> 6;
    float4 pa[8], pw[4];
    {
#pragma unroll
        for (int p = 0; p < 8; p++) {
            int idx = tid + p * 256;
            pa[p] = *(const float4*)(A + (size_t)(idx >> 4) * K + (idx & 15) * 4);
        }
        const float* Wb = W + (size_t)colBase * K;
#pragma unroll
        for (int p = 0; p < 4; p++) {
            int idx = tid + p * 256;
            pw[p] = *(const float4*)(Wb + (size_t)(idx >> 4) * K + (idx & 15) * 4);
        }
    }

    for (int kc = 0; kc < nch; kc++) {
        __syncthreads();
#pragma unroll
        for (int p = 0; p < 8; p++) {
            int idx = tid + p * 256;
            store_split(Ah, Al, idx >> 4, idx & 15, pa[p]);
        }
#pragma unroll
        for (int p = 0; p < 4; p++) {
            int idx = tid + p * 256;
            store_split(Wh, Wl, idx >> 4, idx & 15, pw[p]);
        }
        __syncthreads();
        if (kc + 1 < nch) {
            const float* Ab = A + (kc + 1) * 64;
#pragma unroll
            for (int p = 0; p < 8; p++) {
                int idx = tid + p * 256;
                pa[p] = *(const float4*)(Ab + (size_t)(idx >> 4) * K + (idx & 15) * 4);
            }
            const float* Wb = W + (size_t)colBase * K + (kc + 1) * 64;
#pragma unroll
            for (int p = 0; p < 4; p++) {
                int idx = tid + p * 256;
                pw[p] = *(const float4*)(Wb + (size_t)(idx >> 4) * K + (idx & 15) * 4);
            }
        }
#pragma unroll
        for (int ks = 0; ks < 4; ks++) {
            uint32_t ahf[4][4], alf[4][4];
#pragma unroll
            for (int mt = 0; mt < 4; mt++) {
                uint32_t boff = (uint32_t)((row0 + mt * 16 + a_row) * PITCH + ks * 32 + a_kh);
                ldsm_x4(ahf[mt][0], ahf[mt][1], ahf[mt][2], ahf[mt][3],
                        (uint32_t)__cvta_generic_to_shared(Ah + boff));
                ldsm_x4(alf[mt][0], alf[mt][1], alf[mt][2], alf[mt][3],
                        (uint32_t)__cvta_generic_to_shared(Al + boff));
            }
            uint32_t bhf[2][2], blf[2][2];
#pragma unroll
            for (int nt = 0; nt < 2; nt++) {
                uint32_t boff = (uint32_t)((col0 + nt * 8 + b_nrow) * PITCH + ks * 32 + b_kh);
                ldsm_x2(bhf[nt][0], bhf[nt][1],
                        (uint32_t)__cvta_generic_to_shared(Wh + boff));
                ldsm_x2(blf[nt][0], blf[nt][1],
                        (uint32_t)__cvta_generic_to_shared(Wl + boff));
            }
#pragma unroll
            for (int mt = 0; mt < 4; mt++)
#pragma unroll
                for (int nt = 0; nt < 2; nt++) {
                    mma_bf16(acc[mt][nt], ahf[mt], bhf[nt]);
                    mma_bf16(acc[mt][nt], ahf[mt], blf[nt]);
                    mma_bf16(acc[mt][nt], alf[mt], bhf[nt]);
                }
        }
    }

    // -------- epilogue: dump accs to smem tile, fused BatchNorm -------------
    __syncthreads();
    float* tile = (float*)sm;                       // 128 x 65 fp32
    const int g = lane >> 2, tq = lane & 3;
#pragma unroll
    for (int mt = 0; mt < 4; mt++)
#pragma unroll
        for (int nt = 0; nt < 2; nt++) {
            int rr = row0 + mt * 16 + g;
            int cc = col0 + nt * 8 + tq * 2;
            tile[rr * 65 + cc] = acc[mt][nt][0];
            tile[rr * 65 + cc + 1] = acc[mt][nt][1];
            tile[(rr + 8) * 65 + cc] = acc[mt][nt][2];
            tile[(rr + 8) * 65 + cc + 1] = acc[mt][nt][3];
        }
    __syncthreads();
    float* sm_mu = (float*)(sm + OFF_WH);
    float* sm_rs = sm_mu + 64;
    float* sm_ga = sm_rs + 64;
    float* sm_be = sm_ga + 64;
    if (tid < 64) {
        float s = 0.0f, s2 = 0.0f;
#pragma unroll 8
        for (int r = 0; r < 128; r++) {
            float v = tile[r * 65 + tid];
            s += v;
            s2 += v * v;
        }
        float mu = s * (1.0f / 128.0f);
        float var = s2 * (1.0f / 128.0f) - mu * mu;
        sm_mu[tid] = mu;
        sm_rs[tid] = rsqrtf(var + 1e-5f);
        if (AFFINE_RELU) {
            sm_ga[tid] = gamma[colBase + tid];
            sm_be[tid] = beta[colBase + tid];
        }
    }
    __syncthreads();
#pragma unroll
    for (int p = 0; p < 32; p++) {
        int idx = tid + p * 256;
        int r = idx >> 6, c = idx & 63;
        float v = tile[r * 65 + c];
        float y = (v - sm_mu[c]) * sm_rs[c];
        if (AFFINE_RELU) y = fmaxf(y * sm_ga[c] + sm_be[c], 0.0f);
        Y[(size_t)r * NOUT + colBase + c] = y;
    }
}

// ---------------------------------------------------------------------------
// Gumbel from threefry bits (accurate near u=1); matches JAX uniform+gumbel
// ---------------------------------------------------------------------------
__device__ __forceinline__ float gumbel_from_bits(uint32_t bits) {
    uint32_t mb = bits >> 9;
    float f = __uint_as_float(mb | 0x3f800000u) - 1.0f;
    float u = fmaxf(F32_TINY, f + F32_TINY);
    float d = 1.0f - f;
    float Ls = -(d * (1.0f + d * (0.5f + d * (0.33333334f + d * 0.25f))));
    float L = (d < 0.00390625f) ? Ls : __logf(u);
    return -__logf(-L);
}

__global__ void reset_kernel() { d_key_ready = 0; }

// ---------------------------------------------------------------------------
// scan: blocks 0..127 consume; block 128 produces the sequential key chain.
// No max-subtraction (exp args bounded <= ~45; sum < 1e23 << fp32 max).
// ---------------------------------------------------------------------------
__global__ void __launch_bounds__(512, 1) gumbel_scan_kernel(
    const float* __restrict__ logits, float* __restrict__ z_out) {
    if (blockIdx.x == B_DIM) {
        if (threadIdx.x == 0) {
            uint32_t k0 = 0u, k1 = 42u;
            for (int t = 0; t < K_ITERS; t++) {
                uint32_t kx = k0 ^ k1 ^ 0x1BD11BDAu;
                uint32_t a0, a1, b0, b1;
                threefry2x32(k0, k1, kx, 0u, 0u, a0, a1);  // new key
                threefry2x32(k0, k1, kx, 0u, 1u, b0, b1);  // subkey
                d_subkeys[2 * t] = b0;
                d_subkeys[2 * t + 1] = b1;
                st_release_u32(&d_key_ready, (uint32_t)(t + 1));
                k0 = a0; k1 = a1;
            }
        }
        return;
    }

    const int r = blockIdx.x;
    const int tid = threadIdx.x;
    const int lane = tid & 31;
    const int wid = tid >> 5;
    const uint32_t ibase = (uint32_t)r * 2048u + (uint32_t)tid;

    __shared__ float redB[2][16];
    __shared__ uint32_t skey[64];

    float mask[4], z[4];
#pragma unroll
    for (int i = 0; i < 4; i++) {
        mask[i] = logits[r * C_DIM + tid + 512 * i];
        z[i] = 0.0f;
    }

    for (int t = 0; t < K_ITERS; t++) {
        if ((t & 31) == 0) {
            __syncthreads();   // retire prior skey reads
            if (tid == 0) {
                uint32_t need = (uint32_t)(t + 32);
                while (ld_acquire_u32(&d_key_ready) < need) {}
            }
            __syncthreads();
            if (tid < 64) skey[tid] = d_subkeys[2 * t + tid];
            __syncthreads();
        }
        const uint32_t k0 = skey[(t & 31) * 2];
        const uint32_t k1 = skey[(t & 31) * 2 + 1];
        const uint32_t k2 = k0 ^ k1 ^ 0x1BD11BDAu;

        float e[4];
        float sm = 0.0f;
#pragma unroll
        for (int i = 0; i < 4; i++) {
            uint32_t idx = ibase + 512u * (uint32_t)i;
            uint32_t o0, o1;
            threefry2x32(k0, k1, k2, 0u, idx, o0, o1);
            float g = gumbel_from_bits(o0 ^ o1);
            e[i] = __expf((mask[i] + g) * 2.0f);   // /TAU, TAU=0.5
            sm += e[i];
        }
#pragma unroll
        for (int o = 16; o > 0; o >>= 1) sm += __shfl_xor_sync(0xffffffffu, sm, o);
        if (lane == 0) redB[t & 1][wid] = sm;
        __syncthreads();
        sm = redB[t & 1][0];
#pragma unroll
        for (int w = 1; w < 16; w++) sm += redB[t & 1][w];

        float inv = __fdividef(1.0f, sm);
#pragma unroll
        for (int i = 0; i < 4; i++) {
            mask[i] = e[i] * inv;
            z[i] = fmaxf(z[i], mask[i]);
        }
    }

#pragma unroll
    for (int i = 0; i < 4; i++) z_out[r * C_DIM + tid + 512 * i] = z[i];
}

// ---------------------------------------------------------------------------
// Launch
// ---------------------------------------------------------------------------
extern "C" void kernel_launch(void* const* d_in, const int* in_sizes, int n_in,
                              void* d_out, int out_size) {
    const float* f   = (const float*)d_in[0];
    const float* w1  = (const float*)d_in[1];
    const float* g1  = (const float*)d_in[3];
    const float* be1 = (const float*)d_in[4];
    const float* w2  = (const float*)d_in[5];
    const float* g2  = (const float*)d_in[7];
    const float* be2 = (const float*)d_in[8];
    const float* w3  = (const float*)d_in[9];
    float* out = (float*)d_out;

    float* h1;     cudaGetSymbolAddress((void**)&h1, d_h1);
    float* h2;     cudaGetSymbolAddress((void**)&h2, d_h2);
    float* logits; cudaGetSymbolAddress((void**)&logits, d_logits);

    cudaFuncSetAttribute(gemm_bn_kernel<true>,
                         cudaFuncAttributeMaxDynamicSharedMemorySize, GEMM_SMEM_BYTES);
    cudaFuncSetAttribute(gemm_bn_kernel<false>,
                         cudaFuncAttributeMaxDynamicSharedMemorySize, GEMM_SMEM_BYTES);

    // Layer 1: [128,2048] x [8192,2048]^T -> BN+ReLU (bias cancels in BN)
    gemm_bn_kernel<true><<<M_DIM / 64, 256, GEMM_SMEM_BYTES>>>(
        f, w1, g1, be1, h1, D_DIM, M_DIM);
    // Layer 2: [128,8192] x [8192,8192]^T -> BN+ReLU
    gemm_bn_kernel<true><<<M_DIM / 64, 256, GEMM_SMEM_BYTES>>>(
        h1, w2, g2, be2, h2, M_DIM, M_DIM);
    // Layer 3: [128,8192] x [2048,8192]^T -> BN (no affine, no relu)
    gemm_bn_kernel<false><<<C_DIM / 64, 256, GEMM_SMEM_BYTES>>>(
        h2, w3, nullptr, nullptr, logits, M_DIM, C_DIM);

    reset_kernel<<<1, 1>>>();
    gumbel_scan_kernel<<<B_DIM + 1, 512>>>(logits, out);
}

// round 7
// speedup vs baseline: 1.9571x; 1.1344x over previous
#include <cuda_runtime.h>
#include <cuda_bf16.h>
#include <cuda_fp16.h>
#include <cstdint>

// ---------------------------------------------------------------------------
// B=128, D=2048, M=8192, C=2048, K_ITERS=1024, TAU=0.5
// ---------------------------------------------------------------------------
#define B_DIM 128
#define D_DIM 2048
#define M_DIM 8192
#define C_DIM 2048
#define K_ITERS 1024
#define F32_TINY 1.17549435e-38f

// fp16 split activation buffers (ping-pong sets)
__device__ __half d_ah0[B_DIM * M_DIM];
__device__ __half d_al0[B_DIM * M_DIM];
__device__ __half d_ah1[B_DIM * M_DIM];
__device__ __half d_al1[B_DIM * M_DIM];
__device__ float d_logits[B_DIM * C_DIM];
__device__ uint32_t d_subkeys[2 * K_ITERS];
__device__ uint32_t d_key_ready;   // reset by presplit kernel each replay

// ---------------------------------------------------------------------------
// PTX helpers (portable to compute_103)
// ---------------------------------------------------------------------------
__device__ __forceinline__ uint32_t h2_bits(__half2 h) {
    uint32_t u;
    memcpy(&u, &h, 4);
    return u;
}
__device__ __forceinline__ uint32_t ld_acquire_u32(const uint32_t* p) {
    uint32_t v;
    asm volatile("ld.acquire.gpu.global.u32 %0, [%1];" : "=r"(v) : "l"(p) : "memory");
    return v;
}
__device__ __forceinline__ void st_release_u32(uint32_t* p, uint32_t v) {
    asm volatile("st.release.gpu.global.u32 [%0], %1;" :: "l"(p), "r"(v) : "memory");
}
__device__ __forceinline__ void ldsm_x4(uint32_t& r0, uint32_t& r1, uint32_t& r2,
                                        uint32_t& r3, uint32_t addr) {
    asm volatile("ldmatrix.sync.aligned.m8n8.x4.shared.b16 {%0,%1,%2,%3}, [%4];"
                 : "=r"(r0), "=r"(r1), "=r"(r2), "=r"(r3) : "r"(addr));
}
__device__ __forceinline__ void ldsm_x2(uint32_t& r0, uint32_t& r1, uint32_t addr) {
    asm volatile("ldmatrix.sync.aligned.m8n8.x2.shared.b16 {%0,%1}, [%2];"
                 : "=r"(r0), "=r"(r1) : "r"(addr));
}
__device__ __forceinline__ void mma_fp16(float* c, const uint32_t* a, const uint32_t* b) {
    asm volatile(
        "mma.sync.aligned.m16n8k16.row.col.f32.f16.f16.f32 "
        "{%0,%1,%2,%3}, {%4,%5,%6,%7}, {%8,%9}, {%0,%1,%2,%3};"
        : "+f"(c[0]), "+f"(c[1]), "+f"(c[2]), "+f"(c[3])
        : "r"(a[0]), "r"(a[1]), "r"(a[2]), "r"(a[3]), "r"(b[0]), "r"(b[1]));
}
__device__ __forceinline__ void cp_async16(uint32_t dst, const void* src) {
    asm volatile("cp.async.cg.shared.global [%0], [%1], 16;" :: "r"(dst), "l"(src));
}
__device__ __forceinline__ void cp_commit() {
    asm volatile("cp.async.commit_group;" ::: "memory");
}
template <int N>
__device__ __forceinline__ void cp_wait() {
    asm volatile("cp.async.wait_group %0;" :: "n"(N) : "memory");
}

// ---------------------------------------------------------------------------
// threefry2x32 (JAX-exact, partitionable semantics)
// ---------------------------------------------------------------------------
__device__ __forceinline__ void tf_round(uint32_t& x0, uint32_t& x1, int d) {
    x0 += x1;
    x1 = __funnelshift_l(x1, x1, d);
    x1 ^= x0;
}
__device__ __forceinline__ void threefry2x32(uint32_t k0, uint32_t k1, uint32_t k2,
                                             uint32_t x0, uint32_t x1,
                                             uint32_t& o0, uint32_t& o1) {
    x0 += k0; x1 += k1;
    tf_round(x0, x1, 13); tf_round(x0, x1, 15); tf_round(x0, x1, 26); tf_round(x0, x1, 6);
    x0 += k1; x1 += k2 + 1u;
    tf_round(x0, x1, 17); tf_round(x0, x1, 29); tf_round(x0, x1, 16); tf_round(x0, x1, 24);
    x0 += k2; x1 += k0 + 2u;
    tf_round(x0, x1, 13); tf_round(x0, x1, 15); tf_round(x0, x1, 26); tf_round(x0, x1, 6);
    x0 += k0; x1 += k1 + 3u;
    tf_round(x0, x1, 17); tf_round(x0, x1, 29); tf_round(x0, x1, 16); tf_round(x0, x1, 24);
    x0 += k1; x1 += k2 + 4u;
    tf_round(x0, x1, 13); tf_round(x0, x1, 15); tf_round(x0, x1, 26); tf_round(x0, x1, 6);
    x0 += k2; x1 += k0 + 5u;
    o0 = x0; o1 = x1;
}

// ---------------------------------------------------------------------------
// presplit: f fp32 -> fp16 hi/lo pair; also resets the key-chain flag
// ---------------------------------------------------------------------------
__global__ void presplit_kernel(const float* __restrict__ f,
                                __half* __restrict__ Ah, __half* __restrict__ Al, int n) {
    int i = blockIdx.x * blockDim.x + threadIdx.x;
    if (i == 0) d_key_ready = 0;
    if (i < n) {
        float v = f[i];
        __half h = __float2half_rn(v);
        Ah[i] = h;
        Al[i] = __float2half_rn(v - __half2float(h));
    }
}

// ---------------------------------------------------------------------------
// GEMM(+fused BN/ReLU): Y[128, NOUT], block tile 128 x NTILE, BK=64, 2 stages.
// A pre-split fp16 hi/lo in gmem (cp.async straight to smem); W fp32 -> fp16
// hi/lo split in registers. 3-pass mma: Ah*Wh + Ah*Wl + Al*Wh.
// smem pitch 144B per 64-col fp16 row (conflict-free ldmatrix).
// ---------------------------------------------------------------------------
#define PITCH 144
#define A_HALF_BYTES 18432            // 128 rows * 144
#define A_BYTES      36864            // hi + lo

template <int NTILE>
struct GemmCfg {
    static constexpr int W_HALF = NTILE * PITCH;
    static constexpr int STAGE = A_BYTES + 2 * W_HALF;
    static constexpr int SMEM = 2 * STAGE;
    static constexpr int WPT = NTILE / 16;          // W float4 loads / thread
    static constexpr int MT = (NTILE == 64) ? 4 : 1;
};

__device__ __forceinline__ void issue_A(uint32_t sb, const __half* Ah_g,
                                        const __half* Al_g, int K, int kc, int tid) {
#pragma unroll
    for (int p = 0; p < 8; p++) {
        int idx = tid + p * 256;            // 0..2047 16B chunks
        int hsel = idx >> 10;
        int rem = idx & 1023;
        int row = rem >> 3, seg = rem & 7;
        const __half* src = (hsel ? Al_g : Ah_g) + (size_t)row * K + kc * 64 + seg * 8;
        uint32_t dst = sb + hsel * A_HALF_BYTES + row * PITCH + seg * 16;
        cp_async16(dst, src);
    }
}

__device__ __forceinline__ void sts_W_split(char* wh, char* wl, int row, int c4, float4 v) {
    __half2 h01 = __floats2half2_rn(v.x, v.y);
    __half2 h23 = __floats2half2_rn(v.z, v.w);
    float2 f01 = __half22float2(h01);
    float2 f23 = __half22float2(h23);
    __half2 l01 = __floats2half2_rn(v.x - f01.x, v.y - f01.y);
    __half2 l23 = __floats2half2_rn(v.z - f23.x, v.w - f23.y);
    uint32_t off = (uint32_t)(row * PITCH + c4 * 8);
    *(uint2*)(wh + off) = make_uint2(h2_bits(h01), h2_bits(h23));
    *(uint2*)(wl + off) = make_uint2(h2_bits(l01), h2_bits(l23));
}

template <int NTILE, bool AFFINE_RELU, bool WRITE_SPLIT>
__global__ void __launch_bounds__(256, 1) gemm_bn_kernel(
    const __half* __restrict__ Ah_g, const __half* __restrict__ Al_g,
    const float* __restrict__ W,
    const float* __restrict__ gamma, const float* __restrict__ beta,
    float* __restrict__ Yf, __half* __restrict__ Yh, __half* __restrict__ Yl,
    int K, int NOUT) {
    using C = GemmCfg<NTILE>;
    extern __shared__ char sm[];
    const uint32_t smb = (uint32_t)__cvta_generic_to_shared(sm);

    const int tid = threadIdx.x;
    const int wid = tid >> 5;
    const int lane = tid & 31;
    const int colBase = blockIdx.x * NTILE;

    const int row0 = (NTILE == 64) ? (wid >> 2) * 64 : wid * 16;
    const int col0 = (NTILE == 64) ? (wid & 3) * 16 : 0;
    const int a_sub = lane >> 3;
    const int a_row = (a_sub & 1) * 8 + (lane & 7);
    const int a_kh = (a_sub >> 1) * 16;
    const int b_nrow = lane & 7;
    const int b_kh = ((lane >> 3) & 1) * 16;

    float acc[C::MT][2][4];
#pragma unroll
    for (int mt = 0; mt < C::MT; mt++)
#pragma unroll
        for (int nt = 0; nt < 2; nt++)
#pragma unroll
            for (int i = 0; i < 4; i++) acc[mt][nt][i] = 0.0f;

    const int nch = K >> 6;
    float4 wr[C::WPT];

    issue_A(smb, Ah_g, Al_g, K, 0, tid);
    cp_commit();
    {
        const float* Wb = W + (size_t)colBase * K;
#pragma unroll
        for (int p = 0; p < C::WPT; p++) {
            int idx = tid + p * 256;
            wr[p] = *(const float4*)(Wb + (size_t)(idx >> 4) * K + (idx & 15) * 4);
        }
    }

    for (int kc = 0; kc < nch; kc++) {
        const int s = kc & 1;
        const uint32_t sb = smb + s * C::STAGE;
        char* sb_p = sm + s * C::STAGE;

        if (kc + 1 < nch) issue_A(smb + (s ^ 1) * C::STAGE, Ah_g, Al_g, K, kc + 1, tid);
        cp_commit();

        // convert+store W(kc) from regs
        char* whp = sb_p + A_BYTES;
        char* wlp = sb_p + A_BYTES + C::W_HALF;
#pragma unroll
        for (int p = 0; p < C::WPT; p++) {
            int idx = tid + p * 256;
            sts_W_split(whp, wlp, idx >> 4, idx & 15, wr[p]);
        }
        // prefetch W(kc+1)
        if (kc + 1 < nch) {
            const float* Wb = W + (size_t)colBase * K + (kc + 1) * 64;
#pragma unroll
            for (int p = 0; p < C::WPT; p++) {
                int idx = tid + p * 256;
                wr[p] = *(const float4*)(Wb + (size_t)(idx >> 4) * K + (idx & 15) * 4);
            }
        }
        cp_wait<1>();           // A(kc) resident (A(kc+1) may be in flight)
        __syncthreads();

        const uint32_t ah_b = sb;
        const uint32_t al_b = sb + A_HALF_BYTES;
        const uint32_t wh_b = sb + A_BYTES;
        const uint32_t wl_b = sb + A_BYTES + C::W_HALF;
#pragma unroll
        for (int ks = 0; ks < 4; ks++) {
            uint32_t ahf[C::MT][4], alf[C::MT][4];
#pragma unroll
            for (int mt = 0; mt < C::MT; mt++) {
                uint32_t boff = (uint32_t)((row0 + mt * 16 + a_row) * PITCH + ks * 32 + a_kh);
                ldsm_x4(ahf[mt][0], ahf[mt][1], ahf[mt][2], ahf[mt][3], ah_b + boff);
                ldsm_x4(alf[mt][0], alf[mt][1], alf[mt][2], alf[mt][3], al_b + boff);
            }
            uint32_t bhf[2][2], blf[2][2];
#pragma unroll
            for (int nt = 0; nt < 2; nt++) {
                uint32_t boff = (uint32_t)((col0 + nt * 8 + b_nrow) * PITCH + ks * 32 + b_kh);
                ldsm_x2(bhf[nt][0], bhf[nt][1], wh_b + boff);
                ldsm_x2(blf[nt][0], blf[nt][1], wl_b + boff);
            }
#pragma unroll
            for (int mt = 0; mt < C::MT; mt++)
#pragma unroll
                for (int nt = 0; nt < 2; nt++) {
                    mma_fp16(acc[mt][nt], ahf[mt], bhf[nt]);
                    mma_fp16(acc[mt][nt], ahf[mt], blf[nt]);
                    mma_fp16(acc[mt][nt], alf[mt], bhf[nt]);
                }
        }
        __syncthreads();
    }

    // -------- epilogue: smem tile + fused BatchNorm -------------------------
    float* tile = (float*)sm;                       // 128 x (NTILE+1)
    const int TP = NTILE + 1;
    const int g = lane >> 2, tq = lane & 3;
#pragma unroll
    for (int mt = 0; mt < C::MT; mt++)
#pragma unroll
        for (int nt = 0; nt < 2; nt++) {
            int rr = row0 + mt * 16 + g;
            int cc = col0 + nt * 8 + tq * 2;
            tile[rr * TP + cc] = acc[mt][nt][0];
            tile[rr * TP + cc + 1] = acc[mt][nt][1];
            tile[(rr + 8) * TP + cc] = acc[mt][nt][2];
            tile[(rr + 8) * TP + cc + 1] = acc[mt][nt][3];
        }
    __syncthreads();
    float* stats = (float*)(sm + ((128 * TP * 4 + 127) & ~127));
    float* sm_mu = stats;
    float* sm_rs = stats + NTILE;
    float* sm_ga = stats + 2 * NTILE;
    float* sm_be = stats + 3 * NTILE;
    if (tid < NTILE) {
        float s = 0.0f, s2 = 0.0f;
#pragma unroll 8
        for (int r = 0; r < 128; r++) {
            float v = tile[r * TP + tid];
            s += v;
            s2 += v * v;
        }
        float mu = s * (1.0f / 128.0f);
        float var = s2 * (1.0f / 128.0f) - mu * mu;
        sm_mu[tid] = mu;
        sm_rs[tid] = rsqrtf(var + 1e-5f);
        if (AFFINE_RELU) {
            sm_ga[tid] = gamma[colBase + tid];
            sm_be[tid] = beta[colBase + tid];
        }
    }
    __syncthreads();
#pragma unroll
    for (int p = 0; p < NTILE / 2; p++) {
        int idx = tid + p * 256;
        int r = idx / NTILE, c = idx % NTILE;
        float v = tile[r * TP + c];
        float y = (v - sm_mu[c]) * sm_rs[c];
        if (AFFINE_RELU) y = fmaxf(y * sm_ga[c] + sm_be[c], 0.0f);
        size_t o = (size_t)r * NOUT + colBase + c;
        if (WRITE_SPLIT) {
            __half h = __float2half_rn(y);
            Yh[o] = h;
            Yl[o] = __float2half_rn(y - __half2float(h));
        } else {
            Yf[o] = y;
        }
    }
}

// ---------------------------------------------------------------------------
// Gumbel from threefry bits (accurate near u=1); matches JAX uniform+gumbel
// ---------------------------------------------------------------------------
__device__ __forceinline__ float gumbel_from_bits(uint32_t bits) {
    uint32_t mb = bits >> 9;
    float f = __uint_as_float(mb | 0x3f800000u) - 1.0f;
    float u = fmaxf(F32_TINY, f + F32_TINY);
    float d = 1.0f - f;
    float Ls = -(d * (1.0f + d * (0.5f + d * (0.33333334f + d * 0.25f))));
    float L = (d < 0.00390625f) ? Ls : __logf(u);
    return -__logf(-L);
}

// ---------------------------------------------------------------------------
// scan: blocks 0..127 consume; block 128 produces the sequential key chain.
// No max-subtraction (exp args bounded; sum << fp32 max).
// ---------------------------------------------------------------------------
__global__ void __launch_bounds__(512, 1) gumbel_scan_kernel(
    const float* __restrict__ logits, float* __restrict__ z_out) {
    if (blockIdx.x == B_DIM) {
        if (threadIdx.x == 0) {
            uint32_t k0 = 0u, k1 = 42u;
            for (int t = 0; t < K_ITERS; t++) {
                uint32_t kx = k0 ^ k1 ^ 0x1BD11BDAu;
                uint32_t a0, a1, b0, b1;
                threefry2x32(k0, k1, kx, 0u, 0u, a0, a1);  // new key
                threefry2x32(k0, k1, kx, 0u, 1u, b0, b1);  // subkey
                d_subkeys[2 * t] = b0;
                d_subkeys[2 * t + 1] = b1;
                st_release_u32(&d_key_ready, (uint32_t)(t + 1));
                k0 = a0; k1 = a1;
            }
        }
        return;
    }

    const int r = blockIdx.x;
    const int tid = threadIdx.x;
    const int lane = tid & 31;
    const int wid = tid >> 5;
    const uint32_t ibase = (uint32_t)r * 2048u + (uint32_t)tid;

    __shared__ float redB[2][16];
    __shared__ uint32_t skey[64];

    float mask[4], z[4];
#pragma unroll
    for (int i = 0; i < 4; i++) {
        mask[i] = logits[r * C_DIM + tid + 512 * i];
        z[i] = 0.0f;
    }

    for (int t = 0; t < K_ITERS; t++) {
        if ((t & 31) == 0) {
            __syncthreads();
            if (tid == 0) {
                uint32_t need = (uint32_t)(t + 32);
                while (ld_acquire_u32(&d_key_ready) < need) {}
            }
            __syncthreads();
            if (tid < 64) skey[tid] = d_subkeys[2 * t + tid];
            __syncthreads();
        }
        const uint32_t k0 = skey[(t & 31) * 2];
        const uint32_t k1 = skey[(t & 31) * 2 + 1];
        const uint32_t k2 = k0 ^ k1 ^ 0x1BD11BDAu;

        float e[4];
        float sm = 0.0f;
#pragma unroll
        for (int i = 0; i < 4; i++) {
            uint32_t idx = ibase + 512u * (uint32_t)i;
            uint32_t o0, o1;
            threefry2x32(k0, k1, k2, 0u, idx, o0, o1);
            float g = gumbel_from_bits(o0 ^ o1);
            e[i] = __expf((mask[i] + g) * 2.0f);   // /TAU, TAU=0.5
            sm += e[i];
        }
#pragma unroll
        for (int o = 16; o > 0; o >>= 1) sm += __shfl_xor_sync(0xffffffffu, sm, o);
        if (lane == 0) redB[t & 1][wid] = sm;
        __syncthreads();
        sm = redB[t & 1][0];
#pragma unroll
        for (int w = 1; w < 16; w++) sm += redB[t & 1][w];

        float inv = __fdividef(1.0f, sm);
#pragma unroll
        for (int i = 0; i < 4; i++) {
            mask[i] = e[i] * inv;
            z[i] = fmaxf(z[i], mask[i]);
        }
    }

#pragma unroll
    for (int i = 0; i < 4; i++) z_out[r * C_DIM + tid + 512 * i] = z[i];
}

// ---------------------------------------------------------------------------
// Launch
// ---------------------------------------------------------------------------
extern "C" void kernel_launch(void* const* d_in, const int* in_sizes, int n_in,
                              void* d_out, int out_size) {
    const float* f   = (const float*)d_in[0];
    const float* w1  = (const float*)d_in[1];
    const float* g1  = (const float*)d_in[3];
    const float* be1 = (const float*)d_in[4];
    const float* w2  = (const float*)d_in[5];
    const float* g2  = (const float*)d_in[7];
    const float* be2 = (const float*)d_in[8];
    const float* w3  = (const float*)d_in[9];
    float* out = (float*)d_out;

    __half* ah0; cudaGetSymbolAddress((void**)&ah0, d_ah0);
    __half* al0; cudaGetSymbolAddress((void**)&al0, d_al0);
    __half* ah1; cudaGetSymbolAddress((void**)&ah1, d_ah1);
    __half* al1; cudaGetSymbolAddress((void**)&al1, d_al1);
    float* logits; cudaGetSymbolAddress((void**)&logits, d_logits);

    constexpr int SMEM64 = GemmCfg<64>::SMEM;   // 110592
    constexpr int SMEM16 = GemmCfg<16>::SMEM;   // 82944
    cudaFuncSetAttribute(gemm_bn_kernel<64, true, true>,
                         cudaFuncAttributeMaxDynamicSharedMemorySize, SMEM64);
    cudaFuncSetAttribute(gemm_bn_kernel<16, false, false>,
                         cudaFuncAttributeMaxDynamicSharedMemorySize, SMEM16);

    // split f into fp16 hi/lo (set 0); also resets key flag
    presplit_kernel<<<(B_DIM * D_DIM + 255) / 256, 256>>>(f, ah0, al0, B_DIM * D_DIM);

    // L1: [128,2048] x [8192,2048]^T -> BN+ReLU -> split set1 (bias cancels)
    gemm_bn_kernel<64, true, true><<<M_DIM / 64, 256, SMEM64>>>(
        ah0, al0, w1, g1, be1, nullptr, ah1, al1, D_DIM, M_DIM);
    // L2: [128,8192] x [8192,8192]^T -> BN+ReLU -> split set0
    gemm_bn_kernel<64, true, true><<<M_DIM / 64, 256, SMEM64>>>(
        ah1, al1, w2, g2, be2, nullptr, ah0, al0, M_DIM, M_DIM);
    // L3: [128,8192] x [2048,8192]^T -> BN -> fp32 logits (128 blocks)
    gemm_bn_kernel<16, false, false><<<C_DIM / 16, 256, SMEM16>>>(
        ah0, al0, w3, nullptr, nullptr, logits, nullptr, nullptr, M_DIM, C_DIM);

    gumbel_scan_kernel<<<B_DIM + 1, 512>>>(logits, out);
}

// round 8
// speedup vs baseline: 1.9701x; 1.0066x over previous
#include <cuda_runtime.h>
#include <cuda_bf16.h>
#include <cuda_fp16.h>
#include <cstdint>
#include <cstring>

// ---------------------------------------------------------------------------
// B=128, D=2048, M=8192, C=2048, K_ITERS=1024, TAU=0.5
// ---------------------------------------------------------------------------
#define B_DIM 128
#define D_DIM 2048
#define M_DIM 8192
#define C_DIM 2048
#define K_ITERS 1024
#define F32_TINY 1.17549435e-38f

// fp16 split activation buffers (ping-pong sets)
__device__ __half d_ah0[B_DIM * M_DIM];
__device__ __half d_al0[B_DIM * M_DIM];
__device__ __half d_ah1[B_DIM * M_DIM];
__device__ __half d_al1[B_DIM * M_DIM];
__device__ float d_logits[B_DIM * C_DIM];
__device__ uint32_t d_subkeys[2 * K_ITERS];
__device__ uint32_t d_key_ready;   // reset by presplit kernel each replay

// ---------------------------------------------------------------------------
// PTX helpers (portable to compute_103)
// ---------------------------------------------------------------------------
__device__ __forceinline__ uint32_t h2_bits(__half2 h) {
    uint32_t u;
    memcpy(&u, &h, 4);
    return u;
}
__device__ __forceinline__ uint32_t ld_acquire_u32(const uint32_t* p) {
    uint32_t v;
    asm volatile("ld.acquire.gpu.global.u32 %0, [%1];" : "=r"(v) : "l"(p) : "memory");
    return v;
}
__device__ __forceinline__ void st_release_u32(uint32_t* p, uint32_t v) {
    asm volatile("st.release.gpu.global.u32 [%0], %1;" :: "l"(p), "r"(v) : "memory");
}
__device__ __forceinline__ void ldsm_x4(uint32_t& r0, uint32_t& r1, uint32_t& r2,
                                        uint32_t& r3, uint32_t addr) {
    asm volatile("ldmatrix.sync.aligned.m8n8.x4.shared.b16 {%0,%1,%2,%3}, [%4];"
                 : "=r"(r0), "=r"(r1), "=r"(r2), "=r"(r3) : "r"(addr));
}
__device__ __forceinline__ void ldsm_x2(uint32_t& r0, uint32_t& r1, uint32_t addr) {
    asm volatile("ldmatrix.sync.aligned.m8n8.x2.shared.b16 {%0,%1}, [%2];"
                 : "=r"(r0), "=r"(r1) : "r"(addr));
}
__device__ __forceinline__ void mma_fp16(float* c, const uint32_t* a, const uint32_t* b) {
    asm volatile(
        "mma.sync.aligned.m16n8k16.row.col.f32.f16.f16.f32 "
        "{%0,%1,%2,%3}, {%4,%5,%6,%7}, {%8,%9}, {%0,%1,%2,%3};"
        : "+f"(c[0]), "+f"(c[1]), "+f"(c[2]), "+f"(c[3])
        : "r"(a[0]), "r"(a[1]), "r"(a[2]), "r"(a[3]), "r"(b[0]), "r"(b[1]));
}
__device__ __forceinline__ void cp_async16(uint32_t dst, const void* src) {
    asm volatile("cp.async.cg.shared.global [%0], [%1], 16;" :: "r"(dst), "l"(src));
}
__device__ __forceinline__ void cp_commit() {
    asm volatile("cp.async.commit_group;" ::: "memory");
}
template <int N>
__device__ __forceinline__ void cp_wait() {
    asm volatile("cp.async.wait_group %0;" :: "n"(N) : "memory");
}

// ---------------------------------------------------------------------------
// threefry2x32 (JAX-exact, partitionable semantics)
// ---------------------------------------------------------------------------
__device__ __forceinline__ void tf_round(uint32_t& x0, uint32_t& x1, int d) {
    x0 += x1;
    x1 = __funnelshift_l(x1, x1, d);
    x1 ^= x0;
}
__device__ __forceinline__ void threefry2x32(uint32_t k0, uint32_t k1, uint32_t k2,
                                             uint32_t x0, uint32_t x1,
                                             uint32_t& o0, uint32_t& o1) {
    x0 += k0; x1 += k1;
    tf_round(x0, x1, 13); tf_round(x0, x1, 15); tf_round(x0, x1, 26); tf_round(x0, x1, 6);
    x0 += k1; x1 += k2 + 1u;
    tf_round(x0, x1, 17); tf_round(x0, x1, 29); tf_round(x0, x1, 16); tf_round(x0, x1, 24);
    x0 += k2; x1 += k0 + 2u;
    tf_round(x0, x1, 13); tf_round(x0, x1, 15); tf_round(x0, x1, 26); tf_round(x0, x1, 6);
    x0 += k0; x1 += k1 + 3u;
    tf_round(x0, x1, 17); tf_round(x0, x1, 29); tf_round(x0, x1, 16); tf_round(x0, x1, 24);
    x0 += k1; x1 += k2 + 4u;
    tf_round(x0, x1, 13); tf_round(x0, x1, 15); tf_round(x0, x1, 26); tf_round(x0, x1, 6);
    x0 += k2; x1 += k0 + 5u;
    o0 = x0; o1 = x1;
}

// ---------------------------------------------------------------------------
// presplit: f fp32 -> fp16 hi/lo pair; also resets the key-chain flag
// ---------------------------------------------------------------------------
__global__ void presplit_kernel(const float* __restrict__ f,
                                __half* __restrict__ Ah, __half* __restrict__ Al, int n) {
    int i = blockIdx.x * blockDim.x + threadIdx.x;
    if (i == 0) d_key_ready = 0;
    if (i < n) {
        float v = f[i];
        __half h = __float2half_rn(v);
        Ah[i] = h;
        Al[i] = __float2half_rn(v - __half2float(h));
    }
}

// ---------------------------------------------------------------------------
// GEMM(+fused BN/ReLU): Y[128, NOUT], block tile 128 x NTILE, BK=64, 2 stages.
// A pre-split fp16 hi/lo in gmem (cp.async straight to smem); W fp32 -> fp16
// hi/lo split in registers. 3-pass mma: Ah*Wh + Ah*Wl + Al*Wh.
// smem pitch 144B per 64-col fp16 row (conflict-free ldmatrix).
// NTILE<=32 keeps STAGE small enough for 2 CTAs/SM (the R8 occupancy play).
// ---------------------------------------------------------------------------
#define PITCH 144
#define A_HALF_BYTES 18432            // 128 rows * 144
#define A_BYTES      36864            // hi + lo

template <int NTILE>
struct GemmCfg {
    static constexpr int W_HALF = NTILE * PITCH;
    static constexpr int STAGE = A_BYTES + 2 * W_HALF;
    static constexpr int SMEM = 2 * STAGE;
    static constexpr int WPT = NTILE / 16;          // W float4 loads / thread
    static constexpr int WARPS_N = (NTILE == 64) ? 4 : (NTILE == 32 ? 2 : 1);
    static constexpr int WARPS_M = 8 / WARPS_N;
    static constexpr int MT = 128 / (WARPS_M * 16);
};

__device__ __forceinline__ void issue_A(uint32_t sb, const __half* Ah_g,
                                        const __half* Al_g, int K, int kc, int tid) {
#pragma unroll
    for (int p = 0; p < 8; p++) {
        int idx = tid + p * 256;            // 0..2047 16B chunks
        int hsel = idx >> 10;
        int rem = idx & 1023;
        int row = rem >> 3, seg = rem & 7;
        const __half* src = (hsel ? Al_g : Ah_g) + (size_t)row * K + kc * 64 + seg * 8;
        uint32_t dst = sb + hsel * A_HALF_BYTES + row * PITCH + seg * 16;
        cp_async16(dst, src);
    }
}

__device__ __forceinline__ void sts_W_split(char* wh, char* wl, int row, int c4, float4 v) {
    __half2 h01 = __floats2half2_rn(v.x, v.y);
    __half2 h23 = __floats2half2_rn(v.z, v.w);
    float2 f01 = __half22float2(h01);
    float2 f23 = __half22float2(h23);
    __half2 l01 = __floats2half2_rn(v.x - f01.x, v.y - f01.y);
    __half2 l23 = __floats2half2_rn(v.z - f23.x, v.w - f23.y);
    uint32_t off = (uint32_t)(row * PITCH + c4 * 8);
    *(uint2*)(wh + off) = make_uint2(h2_bits(h01), h2_bits(h23));
    *(uint2*)(wl + off) = make_uint2(h2_bits(l01), h2_bits(l23));
}

template <int NTILE, bool AFFINE_RELU, bool WRITE_SPLIT>
__global__ void __launch_bounds__(256, 2) gemm_bn_kernel(
    const __half* __restrict__ Ah_g, const __half* __restrict__ Al_g,
    const float* __restrict__ W,
    const float* __restrict__ gamma, const float* __restrict__ beta,
    float* __restrict__ Yf, __half* __restrict__ Yh, __half* __restrict__ Yl,
    int K, int NOUT) {
    using C = GemmCfg<NTILE>;
    extern __shared__ char sm[];
    const uint32_t smb = (uint32_t)__cvta_generic_to_shared(sm);

    const int tid = threadIdx.x;
    const int wid = tid >> 5;
    const int lane = tid & 31;
    const int colBase = blockIdx.x * NTILE;

    const int row0 = (wid / C::WARPS_N) * (C::MT * 16);
    const int col0 = (wid % C::WARPS_N) * 16;
    const int a_sub = lane >> 3;
    const int a_row = (a_sub & 1) * 8 + (lane & 7);
    const int a_kh = (a_sub >> 1) * 16;
    const int b_nrow = lane & 7;
    const int b_kh = ((lane >> 3) & 1) * 16;

    float acc[C::MT][2][4];
#pragma unroll
    for (int mt = 0; mt < C::MT; mt++)
#pragma unroll
        for (int nt = 0; nt < 2; nt++)
#pragma unroll
            for (int i = 0; i < 4; i++) acc[mt][nt][i] = 0.0f;

    const int nch = K >> 6;
    float4 wr[C::WPT];

    issue_A(smb, Ah_g, Al_g, K, 0, tid);
    cp_commit();
    {
        const float* Wb = W + (size_t)colBase * K;
#pragma unroll
        for (int p = 0; p < C::WPT; p++) {
            int idx = tid + p * 256;
            wr[p] = *(const float4*)(Wb + (size_t)(idx >> 4) * K + (idx & 15) * 4);
        }
    }

    for (int kc = 0; kc < nch; kc++) {
        const int s = kc & 1;
        const uint32_t sb = smb + s * C::STAGE;
        char* sb_p = sm + s * C::STAGE;

        if (kc + 1 < nch) issue_A(smb + (s ^ 1) * C::STAGE, Ah_g, Al_g, K, kc + 1, tid);
        cp_commit();

        // convert+store W(kc) from regs
        char* whp = sb_p + A_BYTES;
        char* wlp = sb_p + A_BYTES + C::W_HALF;
#pragma unroll
        for (int p = 0; p < C::WPT; p++) {
            int idx = tid + p * 256;
            sts_W_split(whp, wlp, idx >> 4, idx & 15, wr[p]);
        }
        // prefetch W(kc+1)
        if (kc + 1 < nch) {
            const float* Wb = W + (size_t)colBase * K + (kc + 1) * 64;
#pragma unroll
            for (int p = 0; p < C::WPT; p++) {
                int idx = tid + p * 256;
                wr[p] = *(const float4*)(Wb + (size_t)(idx >> 4) * K + (idx & 15) * 4);
            }
        }
        cp_wait<1>();           // A(kc) resident (A(kc+1) may be in flight)
        __syncthreads();

        const uint32_t ah_b = sb;
        const uint32_t al_b = sb + A_HALF_BYTES;
        const uint32_t wh_b = sb + A_BYTES;
        const uint32_t wl_b = sb + A_BYTES + C::W_HALF;
#pragma unroll
        for (int ks = 0; ks < 4; ks++) {
            uint32_t ahf[C::MT][4], alf[C::MT][4];
#pragma unroll
            for (int mt = 0; mt < C::MT; mt++) {
                uint32_t boff = (uint32_t)((row0 + mt * 16 + a_row) * PITCH + ks * 32 + a_kh);
                ldsm_x4(ahf[mt][0], ahf[mt][1], ahf[mt][2], ahf[mt][3], ah_b + boff);
                ldsm_x4(alf[mt][0], alf[mt][1], alf[mt][2], alf[mt][3], al_b + boff);
            }
            uint32_t bhf[2][2], blf[2][2];
#pragma unroll
            for (int nt = 0; nt < 2; nt++) {
                uint32_t boff = (uint32_t)((col0 + nt * 8 + b_nrow) * PITCH + ks * 32 + b_kh);
                ldsm_x2(bhf[nt][0], bhf[nt][1], wh_b + boff);
                ldsm_x2(blf[nt][0], blf[nt][1], wl_b + boff);
            }
#pragma unroll
            for (int mt = 0; mt < C::MT; mt++)
#pragma unroll
                for (int nt = 0; nt < 2; nt++) {
                    mma_fp16(acc[mt][nt], ahf[mt], bhf[nt]);
                    mma_fp16(acc[mt][nt], ahf[mt], blf[nt]);
                    mma_fp16(acc[mt][nt], alf[mt], bhf[nt]);
                }
        }
        __syncthreads();
    }

    // -------- epilogue: smem tile + fused BatchNorm -------------------------
    float* tile = (float*)sm;                       // 128 x (NTILE+1)
    const int TP = NTILE + 1;
    const int g = lane >> 2, tq = lane & 3;
#pragma unroll
    for (int mt = 0; mt < C::MT; mt++)
#pragma unroll
        for (int nt = 0; nt < 2; nt++) {
            int rr = row0 + mt * 16 + g;
            int cc = col0 + nt * 8 + tq * 2;
            tile[rr * TP + cc] = acc[mt][nt][0];
            tile[rr * TP + cc + 1] = acc[mt][nt][1];
            tile[(rr + 8) * TP + cc] = acc[mt][nt][2];
            tile[(rr + 8) * TP + cc + 1] = acc[mt][nt][3];
        }
    __syncthreads();
    float* stats = (float*)(sm + ((128 * TP * 4 + 127) & ~127));
    float* sm_mu = stats;
    float* sm_rs = stats + NTILE;
    float* sm_ga = stats + 2 * NTILE;
    float* sm_be = stats + 3 * NTILE;
    if (tid < NTILE) {
        float s = 0.0f, s2 = 0.0f;
#pragma unroll 8
        for (int r = 0; r < 128; r++) {
            float v = tile[r * TP + tid];
            s += v;
            s2 += v * v;
        }
        float mu = s * (1.0f / 128.0f);
        float var = s2 * (1.0f / 128.0f) - mu * mu;
        sm_mu[tid] = mu;
        sm_rs[tid] = rsqrtf(var + 1e-5f);
        if (AFFINE_RELU) {
            sm_ga[tid] = gamma[colBase + tid];
            sm_be[tid] = beta[colBase + tid];
        }
    }
    __syncthreads();
#pragma unroll
    for (int p = 0; p < NTILE / 2; p++) {
        int idx = tid + p * 256;
        int r = idx / NTILE, c = idx % NTILE;
        float v = tile[r * TP + c];
        float y = (v - sm_mu[c]) * sm_rs[c];
        if (AFFINE_RELU) y = fmaxf(y * sm_ga[c] + sm_be[c], 0.0f);
        size_t o = (size_t)r * NOUT + colBase + c;
        if (WRITE_SPLIT) {
            __half h = __float2half_rn(y);
            Yh[o] = h;
            Yl[o] = __float2half_rn(y - __half2float(h));
        } else {
            Yf[o] = y;
        }
    }
}

// ---------------------------------------------------------------------------
// Gumbel from threefry bits via log2 algebra:
// g = -log(-log u) = 0.36651292 - ln2 * log2(-log2 u)
// series branch keeps inner-log relative accuracy near u -> 1.
// ---------------------------------------------------------------------------
__device__ __forceinline__ float gumbel_from_bits(uint32_t bits) {
    uint32_t mb = bits >> 9;
    float f = __uint_as_float(mb | 0x3f800000u) - 1.0f;   // exact in [0,1)
    float u = f + F32_TINY;
    float d = 1.0f - f;                                    // exact
    float Ls = -(d * (1.0f + d * (0.5f + d * (0.33333334f + d * 0.25f))));
    float t = (d < 0.00390625f) ? Ls * 1.4426950f : __log2f(u);   // log2(u)
    return fmaf(-0.6931472f, __log2f(-t), 0.36651292f);
}

// ---------------------------------------------------------------------------
// scan: blocks 0..127 consume (1024 threads, 2 cols each); block 128 is the
// sequential key-chain producer. No max-subtraction (exp args bounded).
// ---------------------------------------------------------------------------
__global__ void __launch_bounds__(1024, 1) gumbel_scan_kernel(
    const float* __restrict__ logits, float* __restrict__ z_out) {
    if (blockIdx.x == B_DIM) {
        if (threadIdx.x == 0) {
            uint32_t k0 = 0u, k1 = 42u;
            for (int t = 0; t < K_ITERS; t++) {
                uint32_t kx = k0 ^ k1 ^ 0x1BD11BDAu;
                uint32_t a0, a1, b0, b1;
                threefry2x32(k0, k1, kx, 0u, 0u, a0, a1);  // new key
                threefry2x32(k0, k1, kx, 0u, 1u, b0, b1);  // subkey
                d_subkeys[2 * t] = b0;
                d_subkeys[2 * t + 1] = b1;
                st_release_u32(&d_key_ready, (uint32_t)(t + 1));
                k0 = a0; k1 = a1;
            }
        }
        return;
    }

    const int r = blockIdx.x;
    const int tid = threadIdx.x;
    const int lane = tid & 31;
    const int wid = tid >> 5;
    const uint32_t ibase = (uint32_t)r * 2048u + (uint32_t)tid;

    __shared__ float redB[2][32];
    __shared__ uint32_t skey[64];

    float mask[2], z[2];
#pragma unroll
    for (int i = 0; i < 2; i++) {
        mask[i] = logits[r * C_DIM + tid + 1024 * i];
        z[i] = 0.0f;
    }

    for (int t = 0; t < K_ITERS; t++) {
        if ((t & 31) == 0) {
            __syncthreads();
            if (tid == 0) {
                uint32_t need = (uint32_t)(t + 32);
                while (ld_acquire_u32(&d_key_ready) < need) {}
            }
            __syncthreads();
            if (tid < 64) skey[tid] = d_subkeys[2 * t + tid];
            __syncthreads();
        }
        const uint32_t k0 = skey[(t & 31) * 2];
        const uint32_t k1 = skey[(t & 31) * 2 + 1];
        const uint32_t k2 = k0 ^ k1 ^ 0x1BD11BDAu;

        float e[2];
        float sm = 0.0f;
#pragma unroll
        for (int i = 0; i < 2; i++) {
            uint32_t idx = ibase + 1024u * (uint32_t)i;
            uint32_t o0, o1;
            threefry2x32(k0, k1, k2, 0u, idx, o0, o1);
            float g = gumbel_from_bits(o0 ^ o1);
            // exp((mask+g)*2) = exp2((mask+g)*2/ln2)
            e[i] = exp2f((mask[i] + g) * 2.8853901817f);
            sm += e[i];
        }
#pragma unroll
        for (int o = 16; o > 0; o >>= 1) sm += __shfl_xor_sync(0xffffffffu, sm, o);
        if (lane == 0) redB[t & 1][wid] = sm;
        __syncthreads();
        float v = redB[t & 1][lane];       // 32 warps -> 32 partials
#pragma unroll
        for (int o = 16; o > 0; o >>= 1) v += __shfl_xor_sync(0xffffffffu, v, o);
        sm = v;

        float inv = __fdividef(1.0f, sm);
#pragma unroll
        for (int i = 0; i < 2; i++) {
            mask[i] = e[i] * inv;
            z[i] = fmaxf(z[i], mask[i]);
        }
    }

#pragma unroll
    for (int i = 0; i < 2; i++) z_out[r * C_DIM + tid + 1024 * i] = z[i];
}

// ---------------------------------------------------------------------------
// Launch
// ---------------------------------------------------------------------------
extern "C" void kernel_launch(void* const* d_in, const int* in_sizes, int n_in,
                              void* d_out, int out_size) {
    const float* f   = (const float*)d_in[0];
    const float* w1  = (const float*)d_in[1];
    const float* g1  = (const float*)d_in[3];
    const float* be1 = (const float*)d_in[4];
    const float* w2  = (const float*)d_in[5];
    const float* g2  = (const float*)d_in[7];
    const float* be2 = (const float*)d_in[8];
    const float* w3  = (const float*)d_in[9];
    float* out = (float*)d_out;

    __half* ah0; cudaGetSymbolAddress((void**)&ah0, d_ah0);
    __half* al0; cudaGetSymbolAddress((void**)&al0, d_al0);
    __half* ah1; cudaGetSymbolAddress((void**)&ah1, d_ah1);
    __half* al1; cudaGetSymbolAddress((void**)&al1, d_al1);
    float* logits; cudaGetSymbolAddress((void**)&logits, d_logits);

    constexpr int SMEM32 = GemmCfg<32>::SMEM;   // 92160  -> 2 CTAs/SM
    constexpr int SMEM16 = GemmCfg<16>::SMEM;   // 82944  -> 2 CTAs/SM
    cudaFuncSetAttribute(gemm_bn_kernel<32, true, true>,
                         cudaFuncAttributeMaxDynamicSharedMemorySize, SMEM32);
    cudaFuncSetAttribute(gemm_bn_kernel<16, false, false>,
                         cudaFuncAttributeMaxDynamicSharedMemorySize, SMEM16);

    // split f into fp16 hi/lo (set 0); also resets key flag
    presplit_kernel<<<(B_DIM * D_DIM + 255) / 256, 256>>>(f, ah0, al0, B_DIM * D_DIM);

    // L1: [128,2048] x [8192,2048]^T -> BN+ReLU -> split set1 (bias cancels)
    gemm_bn_kernel<32, true, true><<<M_DIM / 32, 256, SMEM32>>>(
        ah0, al0, w1, g1, be1, nullptr, ah1, al1, D_DIM, M_DIM);
    // L2: [128,8192] x [8192,8192]^T -> BN+ReLU -> split set0
    gemm_bn_kernel<32, true, true><<<M_DIM / 32, 256, SMEM32>>>(
        ah1, al1, w2, g2, be2, nullptr, ah0, al0, M_DIM, M_DIM);
    // L3: [128,8192] x [2048,8192]^T -> BN -> fp32 logits
    gemm_bn_kernel<16, false, false><<<C_DIM / 16, 256, SMEM16>>>(
        ah0, al0, w3, nullptr, nullptr, logits, nullptr, nullptr, M_DIM, C_DIM);

    gumbel_scan_kernel<<<B_DIM + 1, 1024>>>(logits, out);
}